// round 6
// baseline (speedup 1.0000x reference)
#include <cuda_runtime.h>
#include <math.h>
#include <stdint.h>

#define Nn 64
#define Cc 256
#define CPC 32              // channels per CTA
#define CLUSTER 8           // CTAs per cluster = one n per cluster
#define Tt 64
#define Vv 25
#define HID 16
#define NG 5
#define TV 1600             // floats per (n,c) slice
#define TV4 400             // float4 per slice
#define SXSTRIDE 1608       // padded slice stride in floats (bank decorrelation)
#define THREADS 512

// Gather tables in __device__ global (L1 gather; NOT __constant__ — divergent
// indexed constant access serializes).
__device__ int d_perm[Vv] = {0,1,2,3,20, 8,9,10,11,23,24, 16,17,18,19, 4,5,6,7,21,22, 12,13,14,15};
__device__ int d_grp [Vv] = {0,0,0,0,0,  1,1,1,1,1,1,     2,2,2,2,     3,3,3,3,3,3,   4,4,4,4};

// SMEM layout (floats): sx[CPC*SXSTRIDE] | avg[256] | max[256] | h[80] | gates[160] | perm/grp ints
#define OFF_AVG   (CPC*SXSTRIDE)
#define OFF_MAX   (OFF_AVG + Cc)
#define OFF_H     (OFF_MAX + Cc)
#define OFF_GATES (OFF_H + NG*HID)
#define OFF_INTS  (OFF_GATES + NG*CPC)
#define SMEM_FLOATS (OFF_INTS + 64)
#define SMEM_BYTES  (SMEM_FLOATS * 4)

__device__ __forceinline__ uint32_t ctarank() {
    uint32_t r; asm("mov.u32 %0, %%cluster_ctarank;" : "=r"(r)); return r;
}
__device__ __forceinline__ float ld_peer_f32(const float* p, uint32_t rank) {
    uint32_t la = (uint32_t)__cvta_generic_to_shared(p);
    uint32_t ra;
    asm("mapa.shared::cluster.u32 %0, %1, %2;" : "=r"(ra) : "r"(la), "r"(rank));
    float v;
    asm volatile("ld.shared::cluster.f32 %0, [%1];" : "=f"(v) : "r"(ra));
    return v;
}
#define CLUSTER_BARRIER() do { \
    asm volatile("barrier.cluster.arrive.aligned;" ::: "memory"); \
    asm volatile("barrier.cluster.wait.aligned;"   ::: "memory"); \
} while (0)

__global__ void __launch_bounds__(THREADS, 1) __cluster_dims__(CLUSTER, 1, 1)
k_fused(const float* __restrict__ x,
        const float* __restrict__ W1s, const float* __restrict__ b1s,
        const float* __restrict__ W2s, const float* __restrict__ b2s,
        float* __restrict__ out) {
    extern __shared__ float smem[];
    float* sx      = smem;
    float* s_avg   = smem + OFF_AVG;
    float* s_max   = smem + OFF_MAX;
    float* s_h     = smem + OFF_H;
    float* s_gates = smem + OFF_GATES;          // [f*CPC + ch]
    int*   s_perm  = (int*)(smem + OFF_INTS);
    int*   s_grp   = s_perm + 32;

    const int tid  = threadIdx.x;
    const uint32_t rank = ctarank();
    const int n    = blockIdx.x / CLUSTER;
    const int c0   = (int)rank * CPC;           // first global channel of this CTA

    if (tid < Vv) { s_perm[tid] = d_perm[tid]; s_grp[tid] = d_grp[tid]; }

    // ---- Phase A: load 32 contiguous slices (204.8 KB) into smem, coalesced ----
    {
        const float4* px = reinterpret_cast<const float4*>(x + ((size_t)(n*Cc + c0)) * TV);
        #pragma unroll
        for (int r = 0; r < CPC*TV4/THREADS; r++) {          // 25 iters
            int i = tid + r * THREADS;
            int s = i / TV4, j = i - s * TV4;
            reinterpret_cast<float4*>(sx + s * SXSTRIDE)[j] = px[i];
        }
    }
    __syncthreads();

    // ---- Phase B: local torso mean/max per channel (from smem) ----
    {
        int ch = tid >> 4;          // 0..31
        int q  = tid & 15;
        const float* base = sx + ch * SXSTRIDE;
        float s = 0.f, m = -__builtin_huge_valf();
        #pragma unroll
        for (int r = 0; r < 4; r++) {
            int o = (q + 16*r) * 25;
            float v0 = base[o], v1 = base[o+1], v2 = base[o+2], v3 = base[o+3], v4 = base[o+20];
            s += ((v0+v1) + (v2+v3)) + v4;
            m  = fmaxf(m, fmaxf(fmaxf(v0,v1), fmaxf(v2,v3)));
            m  = fmaxf(m, v4);
        }
        #pragma unroll
        for (int o = 8; o > 0; o >>= 1) {          // reduce within 16-lane group
            s += __shfl_xor_sync(0xFFFFFFFFu, s, o);
            m  = fmaxf(m, __shfl_xor_sync(0xFFFFFFFFu, m, o));
        }
        if (q == 0) {
            s_avg[c0 + ch] = s * (1.0f / 320.0f);
            s_max[c0 + ch] = m;
        }
    }
    __syncthreads();

    // ---- Stats exchange across cluster (DSMEM) ----
    CLUSTER_BARRIER();                           // peers' stats written
    if (tid < Cc) {
        uint32_t src = (uint32_t)(tid >> 5);     // owning rank of channel tid
        if (src != rank) {
            s_avg[tid] = ld_peer_f32(s_avg + tid, src);
            s_max[tid] = ld_peer_f32(s_max + tid, src);
        }
    }
    CLUSTER_BARRIER();                           // all remote reads done (safe exit later)
    __syncthreads();

    // ---- Phase C: MLP -> gates for this CTA's 32 channels ----
    {
        int warp = tid >> 5, lane = tid & 31;    // 16 warps, 80 tasks
        for (int task = warp; task < NG*HID; task += 16) {
            const float* w1 = W1s + task * Cc;
            float a = 0.f, m = 0.f;
            #pragma unroll
            for (int k = 0; k < 8; k++) {
                float w = w1[lane + 32*k];
                a += s_avg[lane + 32*k] * w;
                m += s_max[lane + 32*k] * w;
            }
            #pragma unroll
            for (int o = 16; o > 0; o >>= 1) {
                a += __shfl_xor_sync(0xFFFFFFFFu, a, o);
                m += __shfl_xor_sync(0xFFFFFFFFu, m, o);
            }
            if (lane == 0) {
                float b = b1s[task];
                s_h[task] = fmaxf(a + b, 0.f) + fmaxf(m + b, 0.f);
            }
        }
        __syncthreads();
        if (tid < NG*CPC) {                      // 160 gate values
            int f  = tid / CPC;
            int ch = tid - f * CPC;
            int c  = c0 + ch;
            const float4* w2 = reinterpret_cast<const float4*>(W2s + ((size_t)(f*Cc + c)) * HID);
            float acc = 2.0f * b2s[f*Cc + c];
            #pragma unroll
            for (int q = 0; q < 4; q++) {
                float4 w = w2[q];
                acc += s_h[f*HID + 4*q + 0] * w.x;
                acc += s_h[f*HID + 4*q + 1] * w.y;
                acc += s_h[f*HID + 4*q + 2] * w.z;
                acc += s_h[f*HID + 4*q + 3] * w.w;
            }
            s_gates[f*CPC + ch] = 1.0f / (1.0f + expf(-acc));
        }
        __syncthreads();
    }

    // ---- Phase D: gated permuted write, straight from smem ----
    {
        float4* pout = reinterpret_cast<float4*>(out + ((size_t)(n*Cc + c0)) * TV);
        #pragma unroll
        for (int r = 0; r < CPC*TV4/THREADS; r++) {          // 25 iters
            int i  = tid + r * THREADS;
            int ch = i / TV4, j4 = i - ch * TV4;
            int e  = 4 * j4;
            int t  = e / 25;
            int vo = e - t * 25;
            const float* bs = sx + ch * SXSTRIDE + t * 25;
            float res[4];
            #pragma unroll
            for (int j = 0; j < 4; j++) {
                res[j] = bs[s_perm[vo]] * s_gates[s_grp[vo]*CPC + ch];
                vo++;
                if (vo == Vv) { vo = 0; bs += Vv; }
            }
            pout[i] = make_float4(res[0], res[1], res[2], res[3]);
        }
    }
}

extern "C" void kernel_launch(void* const* d_in, const int* in_sizes, int n_in,
                              void* d_out, int out_size) {
    const float* x   = (const float*)d_in[0];
    const float* W1s = (const float*)d_in[1];
    const float* b1s = (const float*)d_in[2];
    const float* W2s = (const float*)d_in[3];
    const float* b2s = (const float*)d_in[4];
    float* out = (float*)d_out;

    cudaFuncSetAttribute(k_fused, cudaFuncAttributeMaxDynamicSharedMemorySize, SMEM_BYTES);
    k_fused<<<Nn*CLUSTER, THREADS, SMEM_BYTES>>>(x, W1s, b1s, W2s, b2s, out);
}

// round 8
// speedup vs baseline: 1.5049x; 1.5049x over previous
#include <cuda_runtime.h>
#include <math.h>

#define Nn 64
#define Cc 256
#define Tt 64
#define Vv 25
#define HID 16
#define NG 5
#define TV (Tt*Vv)   // 1600
#define TV4 (TV/4)   // 400

// Scratch (allowed: __device__ globals, no allocation)
__device__ float g_avg[Nn*Cc];
__device__ float g_max[Nn*Cc];
__device__ float g_gates[Nn*NG*Cc];

// Gather tables in __device__ global (L1 gather; NOT __constant__ — divergent
// indexed constant access serializes).
__device__ int d_perm[Vv] = {0,1,2,3,20, 8,9,10,11,23,24, 16,17,18,19, 4,5,6,7,21,22, 12,13,14,15};
__device__ int d_grp [Vv] = {0,0,0,0,0,  1,1,1,1,1,1,     2,2,2,2,     3,3,3,3,3,3,   4,4,4,4};

// ---------------------------------------------------------------------------
// K1: per-(n,c) mean + max over torso joints {0,1,2,3,20} across T.
// 512-thread block handles TWO slices: half-block (200 active threads) per
// slice, fixed joint v per thread (predicate computed once), 8 batched
// coalesced loads. Full-slice read also warms L2 with x for K3.
// ---------------------------------------------------------------------------
__global__ void __launch_bounds__(512) k_reduce(const float* __restrict__ x) {
    int tid  = threadIdx.x;
    int half = tid >> 8;                 // 0 or 1
    int lt   = tid & 255;                // 0..255 within half
    int nc   = blockIdx.x * 2 + half;

    float s = 0.f, m = -__builtin_huge_valf();
    if (lt < 200) {
        int row0 = lt / 25;
        int v = lt - row0 * 25;          // fixed joint for this thread
        bool tor = (v < 4) | (v == 20);
        const float* base = x + (size_t)nc * TV + lt;
        float vals[8];
        #pragma unroll
        for (int r = 0; r < 8; r++) vals[r] = base[200 * r];
        if (tor) {
            #pragma unroll
            for (int r = 0; r < 8; r++) {
                s += vals[r];
                m  = fmaxf(m, vals[r]);
            }
        }
    }
    #pragma unroll
    for (int o = 16; o > 0; o >>= 1) {
        s += __shfl_xor_sync(0xFFFFFFFFu, s, o);
        m  = fmaxf(m, __shfl_xor_sync(0xFFFFFFFFu, m, o));
    }
    __shared__ float sh_s[16], sh_m[16];
    int warp = tid >> 5;                 // 0..15 (first 8 = slice 0, next 8 = slice 1)
    if ((tid & 31) == 0) { sh_s[warp] = s; sh_m[warp] = m; }
    __syncthreads();
    if (lt == 0) {
        float S = 0.f, M = -__builtin_huge_valf();
        #pragma unroll
        for (int w = 0; w < 8; w++) { S += sh_s[half*8 + w]; M = fmaxf(M, sh_m[half*8 + w]); }
        g_avg[nc] = S * (1.0f / 320.0f); // mean over T*5 = 320
        g_max[nc] = M;
    }
}

// ---------------------------------------------------------------------------
// K2: gates[n,f,c] = sigmoid( mlp_f(avg[n,:]) + mlp_f(max[n,:]) )
// One block per n, 256 threads.
// ---------------------------------------------------------------------------
__global__ void __launch_bounds__(256) k_mlp(
        const float* __restrict__ W1s, const float* __restrict__ b1s,
        const float* __restrict__ W2s, const float* __restrict__ b2s) {
    int n   = blockIdx.x;
    int tid = threadIdx.x;
    __shared__ float sA[Cc], sM[Cc], hs[NG*HID];

    sA[tid] = g_avg[n*Cc + tid];
    sM[tid] = g_max[n*Cc + tid];
    __syncthreads();

    int warp = tid >> 5, lane = tid & 31;
    for (int task = warp; task < NG*HID; task += 8) {
        const float* w1 = W1s + task * Cc;
        float a = 0.f, m = 0.f;
        #pragma unroll
        for (int k = 0; k < 8; k++) {
            float w = w1[lane + 32*k];
            a += sA[lane + 32*k] * w;
            m += sM[lane + 32*k] * w;
        }
        #pragma unroll
        for (int o = 16; o > 0; o >>= 1) {
            a += __shfl_xor_sync(0xFFFFFFFFu, a, o);
            m += __shfl_xor_sync(0xFFFFFFFFu, m, o);
        }
        if (lane == 0) {
            float b = b1s[task];
            hs[task] = fmaxf(a + b, 0.f) + fmaxf(m + b, 0.f);
        }
    }
    __syncthreads();

    int c = tid;
    #pragma unroll
    for (int f = 0; f < NG; f++) {
        const float4* w2 = reinterpret_cast<const float4*>(W2s + ((size_t)(f*Cc + c)) * HID);
        float acc = 2.0f * b2s[f*Cc + c];
        #pragma unroll
        for (int q = 0; q < 4; q++) {
            float4 w = w2[q];
            acc += hs[f*HID + 4*q + 0] * w.x;
            acc += hs[f*HID + 4*q + 1] * w.y;
            acc += hs[f*HID + 4*q + 2] * w.z;
            acc += hs[f*HID + 4*q + 3] * w.w;
        }
        g_gates[(n*NG + f)*Cc + c] = 1.0f / (1.0f + expf(-acc));
    }
}

// ---------------------------------------------------------------------------
// K3: out[n,c,t,vo] = x[n,c,t,perm[vo]] * gate[n, grp[vo], c]
// REVERSED block order: reads the MRU tail of K1's L2 footprint first so the
// x re-read hits L2 instead of DRAM. Direct global gather (within-row permute
// is L1-line-efficient, no smem round trip); float4 streaming stores.
// ---------------------------------------------------------------------------
__global__ void __launch_bounds__(256) k_apply(const float* __restrict__ x,
                                               float* __restrict__ out) {
    int nc = (Nn*Cc - 1) - blockIdx.x;   // reversed traversal
    int n = nc >> 8, c = nc & 255;
    __shared__ float sgv[Vv];   // gate value per OUTPUT joint position
    __shared__ int   spv[Vv];   // source joint per OUTPUT joint position
    int tid = threadIdx.x;
    if (tid < Vv) {
        sgv[tid] = g_gates[(n*NG + d_grp[tid])*Cc + c];
        spv[tid] = d_perm[tid];
    }
    __syncthreads();

    const float* px  = x + (size_t)nc * TV;
    float4*      po4 = reinterpret_cast<float4*>(out + (size_t)nc * TV);
    #pragma unroll
    for (int r = 0; r < 2; r++) {
        int i4 = tid + r * 256;
        if (i4 < TV4) {
            int e   = 4 * i4;
            int t   = e / 25;
            int vo  = e - t * 25;
            const float* bs = px + t * 25;
            float res[4];
            #pragma unroll
            for (int j = 0; j < 4; j++) {
                res[j] = __ldg(bs + spv[vo]) * sgv[vo];
                vo++;
                if (vo == Vv) { vo = 0; bs += Vv; }
            }
            __stcs(po4 + i4, make_float4(res[0], res[1], res[2], res[3]));
        }
    }
}

extern "C" void kernel_launch(void* const* d_in, const int* in_sizes, int n_in,
                              void* d_out, int out_size) {
    const float* x   = (const float*)d_in[0];
    const float* W1s = (const float*)d_in[1];
    const float* b1s = (const float*)d_in[2];
    const float* W2s = (const float*)d_in[3];
    const float* b2s = (const float*)d_in[4];
    float* out = (float*)d_out;

    k_reduce<<<(Nn*Cc)/2, 512>>>(x);
    k_mlp<<<Nn, 256>>>(W1s, b1s, W2s, b2s);
    k_apply<<<Nn*Cc, 256>>>(x, out);
}